// round 11
// baseline (speedup 1.0000x reference)
#include <cuda_runtime.h>
#include <math.h>

#define W_   512
#define H_   512
#define HW_  (512 * 512)
#define EPS  1e-8f
#define TW   26              // output columns per pair (26 + 6 halo = 32 lanes)
#define FULLMASK 0xffffffffu

__device__ __forceinline__ float sqrt_approx(float x) {
    float r;
    asm("sqrt.approx.f32 %0, %1;" : "=f"(r) : "f"(x));
    return r;
}

// h[L] = sum_{k=0..6} v[L+k]; lanes >= 26 produce garbage (predicated off later)
__device__ __forceinline__ float hsum7(float v) {
    float d1 = v + __shfl_down_sync(FULLMASK, v, 1);
    float d2 = d1 + __shfl_down_sync(FULLMASK, d1, 2);
    float r4 = __shfl_down_sync(FULLMASK, d1, 4);
    float r6 = __shfl_down_sync(FULLMASK, v, 6);
    return d2 + (r4 + r6);
}

__device__ __forceinline__ float smooth_l1(float a, float b) {
    float d = a - b;
    float ad = fabsf(d);
    return (ad < 1.0f) ? 0.5f * d * d : ad - 0.5f;
}

struct Three { float a0, a1, a2; };

__device__ __forceinline__ Three ld3(const float* __restrict__ X, int off, bool ok) {
    Three s;
    s.a0 = ok ? X[off]           : 0.f;
    s.a1 = ok ? X[off + HW_]     : 0.f;
    s.a2 = ok ? X[off + 2 * HW_] : 0.f;
    return s;
}

// One row for ONE input: consume prefetched row i, prefetch row i+1,
// channel-reduce, horizontal 7-sum (fresh data), ring slot S into vertical
// sums; when i >= 6 compute std and store to this warp's SMEM std buffer.
template <int S>
__device__ __forceinline__ void rowstep(
    const float* __restrict__ X,
    int gx, bool okx, int oy0,
    int& i, Three& nxt, float (&ring)[2][7], float (&vs)[2],
    float* __restrict__ stdsm, int L, float inv_n)
{
    Three cur = nxt;

    {   // prefetch row i+1 (last prefetch discarded; guard predicates OOB)
        const int gy1 = oy0 - 2 + i;
        const bool ok1 = okx && (gy1 >= 0) && (gy1 < H_);
        nxt = ld3(X, (gy1 << 9) + gx, ok1);
    }

    float v  = cur.a0 + cur.a1 + cur.a2;
    float v2 = fmaf(cur.a0, cur.a0, fmaf(cur.a1, cur.a1, cur.a2 * cur.a2));
    float h0 = hsum7(v);
    float h1 = hsum7(v2);

    vs[0] += h0 - ring[0][S]; ring[0][S] = h0;
    vs[1] += h1 - ring[1][S]; ring[1][S] = h1;

    if (i >= 6) {
        float mu = vs[0] * inv_n;
        float sd = sqrt_approx(fmaf(-mu, mu, vs[1] * inv_n) + EPS);
        stdsm[((i - 6) << 5) + L] = sd;
    }
    i++;
}

__global__ __launch_bounds__(128)
void dist_loss_kernel(const float* __restrict__ pred,
                      const float* __restrict__ tgt,
                      float* __restrict__ out)
{
    // 4 warps = 2 pairs; warp w: input = (w&1) ? tgt : pred, pair = w>>1
    __shared__ float stdbuf[4][32 * 32];   // 16 KB
    __shared__ float ws[4];

    const int L  = threadIdx.x & 31;
    const int w  = threadIdx.x >> 5;
    const int pair = w >> 1;
    const int x0 = blockIdx.x * TW;
    const int oy0 = (blockIdx.y << 6) + (pair << 5);  // pair's first output row
    const size_t bofs = (size_t)blockIdx.z * 3 * HW_;
    const float* X = ((w & 1) ? tgt : pred) + bofs;

    const int gx = x0 - 3 + L;
    const bool okx = (gx >= 0) && (gx < W_);
    const float inv_n = 1.0f / 147.0f;

    float ring[2][7];
    float vs[2] = {0.f, 0.f};
#pragma unroll
    for (int j = 0; j < 7; j++) { ring[0][j] = 0.f; ring[1][j] = 0.f; }

    float* stdsm = stdbuf[w];
    int i = 0;

    Three nxt;
    {
        const int gy0 = oy0 - 3;
        const bool ok0 = okx && (gy0 >= 0);
        nxt = ld3(X, (gy0 << 9) + gx, ok0);
    }

    // 38 rows = 5 chunks of 7 ring slots + 3 tail
#pragma unroll 1
    for (int c = 0; c < 5; c++) {
        rowstep<0>(X, gx, okx, oy0, i, nxt, ring, vs, stdsm, L, inv_n);
        rowstep<1>(X, gx, okx, oy0, i, nxt, ring, vs, stdsm, L, inv_n);
        rowstep<2>(X, gx, okx, oy0, i, nxt, ring, vs, stdsm, L, inv_n);
        rowstep<3>(X, gx, okx, oy0, i, nxt, ring, vs, stdsm, L, inv_n);
        rowstep<4>(X, gx, okx, oy0, i, nxt, ring, vs, stdsm, L, inv_n);
        rowstep<5>(X, gx, okx, oy0, i, nxt, ring, vs, stdsm, L, inv_n);
        rowstep<6>(X, gx, okx, oy0, i, nxt, ring, vs, stdsm, L, inv_n);
    }
    rowstep<0>(X, gx, okx, oy0, i, nxt, ring, vs, stdsm, L, inv_n);
    rowstep<1>(X, gx, okx, oy0, i, nxt, ring, vs, stdsm, L, inv_n);
    rowstep<2>(X, gx, okx, oy0, i, nxt, ring, vs, stdsm, L, inv_n);

    __syncthreads();

    // loss pass: each pair's 64 threads walk its 32x32 buffer (26 valid cols)
    float acc = 0.f;
    {
        const int tp = ((w & 1) << 5) + L;        // 0..63 within pair
        const float* sp = stdbuf[pair << 1];
        const float* st = stdbuf[(pair << 1) | 1];
#pragma unroll
        for (int e = 0; e < 16; e++) {
            int idx = tp + (e << 6);
            int col = idx & 31;
            bool valid = (col < TW) && ((x0 + col) < W_);
            float f = smooth_l1(sp[idx], st[idx]);
            acc += valid ? f : 0.f;
        }
    }

    // warp + block reduce
#pragma unroll
    for (int o = 16; o > 0; o >>= 1)
        acc += __shfl_xor_sync(FULLMASK, acc, o);
    if (L == 0) ws[w] = acc;
    __syncthreads();
    if (threadIdx.x == 0) {
        float s = ws[0] + ws[1] + ws[2] + ws[3];
        atomicAdd(out, s * (1.0f / (16.0f * 512.0f * 512.0f)));
    }
}

extern "C" void kernel_launch(void* const* d_in, const int* in_sizes, int n_in,
                              void* d_out, int out_size)
{
    const float* pred = (const float*)d_in[0];
    const float* tgt  = (const float*)d_in[1];
    float* out = (float*)d_out;

    cudaMemsetAsync(out, 0, sizeof(float));

    dim3 block(128, 1, 1);
    // x: 20 tiles, y: 512 / 64 rows per CTA = 8, z: 16  -> 2560 CTAs
    dim3 grid((W_ + TW - 1) / TW, H_ / 64, 16);
    dist_loss_kernel<<<grid, block>>>(pred, tgt, out);
}

// round 12
// speedup vs baseline: 1.5097x; 1.5097x over previous
#include <cuda_runtime.h>
#include <math.h>

#define W_   512
#define H_   512
#define HW_  (512 * 512)
#define EPS  1e-8f
#define TW   26              // output columns per warp (26 + 6 halo = 32 lanes)
#define FULLMASK 0xffffffffu

__device__ __forceinline__ float sqrt_approx(float x) {
    float r;
    asm("sqrt.approx.f32 %0, %1;" : "=f"(r) : "f"(x));
    return r;
}

// h[L] = sum_{k=0..6} v[L+k] over the warp-distributed 32-vector.
// Lanes >= 26 get garbage (shfl self) — outputs there are predicated off.
__device__ __forceinline__ float hsum7(float v) {
    float d1 = v + __shfl_down_sync(FULLMASK, v, 1);     // 2-sum
    float d2 = d1 + __shfl_down_sync(FULLMASK, d1, 2);   // 4-sum
    float r4 = __shfl_down_sync(FULLMASK, d1, 4);        // v[c+4]+v[c+5]
    float r6 = __shfl_down_sync(FULLMASK, v, 6);         // v[c+6]
    return d2 + (r4 + r6);
}

__device__ __forceinline__ float smooth_l1(float a, float b) {
    float d = a - b;
    float ad = fabsf(d);
    return (ad < 1.0f) ? 0.5f * d * d : ad - 0.5f;
}

struct Six { float a0, a1, a2, b0, b1, b2; };

__device__ __forceinline__ Six ld6(const float* __restrict__ P,
                                   const float* __restrict__ T,
                                   int off, bool ok) {
    Six s;
    s.a0 = ok ? P[off]           : 0.f;
    s.a1 = ok ? P[off + HW_]     : 0.f;
    s.a2 = ok ? P[off + 2 * HW_] : 0.f;
    s.b0 = ok ? T[off]           : 0.f;
    s.b1 = ok ? T[off + HW_]     : 0.f;
    s.b2 = ok ? T[off + 2 * HW_] : 0.f;
    return s;
}

// One row step, depth-2 load pipelining: consume nxt0 (row i), shift nxt1
// into nxt0, issue loads for row i+2 into nxt1. Horizontal 7-sum on the
// fresh row data, ring slot S into vertical sums. EMIT is compile-time:
// warm-up rows (0..5) carry no std/loss code at all.
template <int S, bool EMIT>
__device__ __forceinline__ void rowstep(
    const float* __restrict__ P, const float* __restrict__ T,
    int gx, bool okx, bool out_ok, int oy0,
    int& i, Six& nxt0, Six& nxt1, float (&ring)[4][7], float (&vs)[4],
    float& acc, float inv_n)
{
    Six cur = nxt0;
    nxt0 = nxt1;

    {   // prefetch row i+2 (tail prefetches discarded; guard predicates OOB)
        const int gy2 = oy0 - 1 + i;
        const bool ok2 = okx && (gy2 >= 0) && (gy2 < H_);
        nxt1 = ld6(P, T, (gy2 << 9) + gx, ok2);
    }

    float h0, h1, h2, h3;
    {
        float v  = cur.a0 + cur.a1 + cur.a2;
        float v2 = fmaf(cur.a0, cur.a0, fmaf(cur.a1, cur.a1, cur.a2 * cur.a2));
        h0 = hsum7(v);
        h1 = hsum7(v2);
    }
    {
        float v  = cur.b0 + cur.b1 + cur.b2;
        float v2 = fmaf(cur.b0, cur.b0, fmaf(cur.b1, cur.b1, cur.b2 * cur.b2));
        h2 = hsum7(v);
        h3 = hsum7(v2);
    }

    vs[0] += h0 - ring[0][S]; ring[0][S] = h0;
    vs[1] += h1 - ring[1][S]; ring[1][S] = h1;
    vs[2] += h2 - ring[2][S]; ring[2][S] = h2;
    vs[3] += h3 - ring[3][S]; ring[3][S] = h3;

    if (EMIT) {
        float mp = vs[0] * inv_n;
        float sp = sqrt_approx(fmaf(-mp, mp, vs[1] * inv_n) + EPS);
        float mt = vs[2] * inv_n;
        float st = sqrt_approx(fmaf(-mt, mt, vs[3] * inv_n) + EPS);
        float f = smooth_l1(sp, st);
        acc += out_ok ? f : 0.f;
    }
    i++;
}

__global__ __launch_bounds__(128, 6)
void dist_loss_kernel(const float* __restrict__ pred,
                      const float* __restrict__ tgt,
                      float* __restrict__ out)
{
    const int L  = threadIdx.x & 31;
    const int w  = threadIdx.x >> 5;
    const int x0 = blockIdx.x * TW;
    const int oy0 = (blockIdx.y << 7) + (w << 5);     // warp's first output row
    const size_t bofs = (size_t)blockIdx.z * 3 * HW_;
    const float* P = pred + bofs;
    const float* T = tgt + bofs;

    const int gx = x0 - 3 + L;                        // halo-inclusive column
    const bool okx = (gx >= 0) && (gx < W_);
    const bool out_ok = (L < TW) && ((x0 + L) < W_);

    const float inv_n = 1.0f / 147.0f;

    float ring[4][7];
    float vs[4];
#pragma unroll
    for (int a = 0; a < 4; a++) {
        vs[a] = 0.f;
#pragma unroll
        for (int j = 0; j < 7; j++) ring[a][j] = 0.f;
    }

    float acc = 0.f;
    int i = 0;

    // prime the 2-deep pipeline with rows 0 and 1
    Six nxt0, nxt1;
    {
        const int gyA = oy0 - 3;
        const int gyB = oy0 - 2;
        nxt0 = ld6(P, T, (gyA << 9) + gx, okx && (gyA >= 0));
        nxt1 = ld6(P, T, (gyB << 9) + gx, okx && (gyB >= 0));
    }

    // 38 rows: 6 warm-up (slots 0..5, EMIT=false), then 32 emitting rows.
    rowstep<0, false>(P, T, gx, okx, out_ok, oy0, i, nxt0, nxt1, ring, vs, acc, inv_n);
    rowstep<1, false>(P, T, gx, okx, out_ok, oy0, i, nxt0, nxt1, ring, vs, acc, inv_n);
    rowstep<2, false>(P, T, gx, okx, out_ok, oy0, i, nxt0, nxt1, ring, vs, acc, inv_n);
    rowstep<3, false>(P, T, gx, okx, out_ok, oy0, i, nxt0, nxt1, ring, vs, acc, inv_n);
    rowstep<4, false>(P, T, gx, okx, out_ok, oy0, i, nxt0, nxt1, ring, vs, acc, inv_n);
    rowstep<5, false>(P, T, gx, okx, out_ok, oy0, i, nxt0, nxt1, ring, vs, acc, inv_n);
    rowstep<6, true >(P, T, gx, okx, out_ok, oy0, i, nxt0, nxt1, ring, vs, acc, inv_n);
#pragma unroll 1
    for (int c = 0; c < 4; c++) {
        rowstep<0, true>(P, T, gx, okx, out_ok, oy0, i, nxt0, nxt1, ring, vs, acc, inv_n);
        rowstep<1, true>(P, T, gx, okx, out_ok, oy0, i, nxt0, nxt1, ring, vs, acc, inv_n);
        rowstep<2, true>(P, T, gx, okx, out_ok, oy0, i, nxt0, nxt1, ring, vs, acc, inv_n);
        rowstep<3, true>(P, T, gx, okx, out_ok, oy0, i, nxt0, nxt1, ring, vs, acc, inv_n);
        rowstep<4, true>(P, T, gx, okx, out_ok, oy0, i, nxt0, nxt1, ring, vs, acc, inv_n);
        rowstep<5, true>(P, T, gx, okx, out_ok, oy0, i, nxt0, nxt1, ring, vs, acc, inv_n);
        rowstep<6, true>(P, T, gx, okx, out_ok, oy0, i, nxt0, nxt1, ring, vs, acc, inv_n);
    }
    rowstep<0, true>(P, T, gx, okx, out_ok, oy0, i, nxt0, nxt1, ring, vs, acc, inv_n);
    rowstep<1, true>(P, T, gx, okx, out_ok, oy0, i, nxt0, nxt1, ring, vs, acc, inv_n);
    rowstep<2, true>(P, T, gx, okx, out_ok, oy0, i, nxt0, nxt1, ring, vs, acc, inv_n);

    // warp + block reduce
#pragma unroll
    for (int o = 16; o > 0; o >>= 1)
        acc += __shfl_xor_sync(FULLMASK, acc, o);

    __shared__ float ws[4];
    if (L == 0) ws[w] = acc;
    __syncthreads();
    if (threadIdx.x == 0) {
        float s = ws[0] + ws[1] + ws[2] + ws[3];
        atomicAdd(out, s * (1.0f / (16.0f * 512.0f * 512.0f)));
    }
}

extern "C" void kernel_launch(void* const* d_in, const int* in_sizes, int n_in,
                              void* d_out, int out_size)
{
    const float* pred = (const float*)d_in[0];
    const float* tgt  = (const float*)d_in[1];
    float* out = (float*)d_out;

    cudaMemsetAsync(out, 0, sizeof(float));

    dim3 block(128, 1, 1);
    dim3 grid((W_ + TW - 1) / TW, H_ / 128, 16);   // 20 x 4 x 16 = 1280 CTAs
    dist_loss_kernel<<<grid, block>>>(pred, tgt, out);
}